// round 4
// baseline (speedup 1.0000x reference)
#include <cuda_runtime.h>
#include <cstdint>

#define DINL __device__ __forceinline__

// ---------------------------------------------------------------------------
// Precomputed weights in mma-fragment-friendly layouts (tf32-rounded fp32).
// g_w1p: GEMM1 A-operand = W_eff^T [256 x 800] as [kt(25)][ks(4)][mf(16)][r(8)][q(4)] float4
//        float4 = ( WT[n][k], WT[n+8][k], WT[n][k+4], WT[n+8][k+4] ),
//        n = mf*16+r, k = kt*32+ks*8+q.   (mma m16n8k8 A-frag ordering)
// g_w2p: GEMM2 A-operand = w2^T [128 x 256] as [ks(32)][mf(8)][r(8)][q(4)] float4
// g_w3p: GEMM3 A-operand = w3^T padded [16 x 128] as [ks(16)][r(8)][q(4)] float4
// ---------------------------------------------------------------------------
__device__ float4 g_w1p[25 * 4 * 16 * 8 * 4];   // 51200 float4
__device__ float4 g_w2p[32 * 8 * 8 * 4];        //  8192 float4
__device__ float4 g_w3p[16 * 8 * 4];            //   512 float4

DINL float tf32f(float f) { uint32_t u; asm("cvt.rna.tf32.f32 %0, %1;" : "=r"(u) : "f"(f)); return __uint_as_float(u); }
DINL uint32_t tf32u(float f) { uint32_t u; asm("cvt.rna.tf32.f32 %0, %1;" : "=r"(u) : "f"(f)); return u; }

DINL void mma8(float* c, uint32_t a0, uint32_t a1, uint32_t a2, uint32_t a3,
               uint32_t b0, uint32_t b1) {
    asm volatile(
        "mma.sync.aligned.m16n8k8.row.col.f32.tf32.tf32.f32 "
        "{%0,%1,%2,%3}, {%4,%5,%6,%7}, {%8,%9}, {%0,%1,%2,%3};"
        : "+f"(c[0]), "+f"(c[1]), "+f"(c[2]), "+f"(c[3])
        : "r"(a0), "r"(a1), "r"(a2), "r"(a3), "r"(b0), "r"(b1));
}

DINL void cpa16(uint32_t dst, const void* src) {
    asm volatile("cp.async.cg.shared.global [%0], [%1], 16;" :: "r"(dst), "l"(src));
}
DINL void cpa16z(uint32_t dst, const void* src) {
    asm volatile("cp.async.cg.shared.global [%0], [%1], 16, %2;" :: "r"(dst), "l"(src), "r"(0));
}

// ---------------------------------------------------------------------------
// Prep kernel: fold conv into fc1, transpose + tf32-round all weights.
// ---------------------------------------------------------------------------
DINL float weff(int k, int n, const float* cw, const float* w1) {
    if (k >= 784) return 0.f;
    int r = k / 28, c = k % 28;
    float acc = 0.f;
#pragma unroll
    for (int dr = 0; dr < 3; dr++)
#pragma unroll
        for (int dc = 0; dc < 3; dc++) {
            int rr = r - dr, cc = c - dc;
            if (rr >= 0 && rr < 26 && cc >= 0 && cc < 26)
                acc += cw[dr * 3 + dc] * w1[(rr * 26 + cc) * 256 + n];
        }
    return tf32f(acc);
}

__global__ __launch_bounds__(256) void prep_kernel(
    const float* __restrict__ cw, const float* __restrict__ w1,
    const float* __restrict__ w2, const float* __restrict__ w3) {
    int gid = blockIdx.x * 256 + threadIdx.x;
    if (blockIdx.x < 200) {
        int i = gid;                                    // 0..51199
        int q = i & 3, r = (i >> 2) & 7, mf = (i >> 5) & 15, ks = (i >> 9) & 3, kt = i >> 11;
        int k = kt * 32 + ks * 8 + q, n = mf * 16 + r;
        float4 v;
        v.x = weff(k, n, cw, w1);     v.y = weff(k, n + 8, cw, w1);
        v.z = weff(k + 4, n, cw, w1); v.w = weff(k + 4, n + 8, cw, w1);
        g_w1p[i] = v;
    } else if (blockIdx.x < 232) {
        int i = gid - 200 * 256;                        // 0..8191
        int q = i & 3, r = (i >> 2) & 7, mf = (i >> 5) & 7, ks = i >> 8;
        int k = ks * 8 + q, n = mf * 16 + r;
        float4 v;
        v.x = tf32f(w2[k * 128 + n]);       v.y = tf32f(w2[k * 128 + n + 8]);
        v.z = tf32f(w2[(k + 4) * 128 + n]); v.w = tf32f(w2[(k + 4) * 128 + n + 8]);
        g_w2p[i] = v;
    } else {
        int i = gid - 232 * 256;                        // 0..511
        if (i < 512) {
            int q = i & 3, r = (i >> 2) & 7, ks = i >> 5;
            int k = ks * 8 + q;
            float4 v;
            v.x = tf32f(w3[k * 10 + r]);
            v.y = (r + 8 < 10) ? tf32f(w3[k * 10 + r + 8]) : 0.f;
            v.z = tf32f(w3[(k + 4) * 10 + r]);
            v.w = (r + 8 < 10) ? tf32f(w3[(k + 4) * 10 + r + 8]) : 0.f;
            g_w3p[i] = v;
        }
    }
}

// ---------------------------------------------------------------------------
// Fused main kernel. Per CTA: 128 batch rows. Batch = N operand of mma.
// smem (floats):
//   phase A (aliased with h1T/h2T): 4 stages x [x 128x36 | w1p 8192] = 51200
//   h1T [256][136]  at 0      (34816 floats)
//   h2T [128][136]  at 34816  (17408 floats, ends 52224)
//   w3p (512 f4)    at 52224  (2048 floats)
//   b1/b2/b3        at 54272 / 54528 / 54656
// ---------------------------------------------------------------------------
constexpr int XS = 36, H1S = 136, H2S = 136;
constexpr int XBUF = 128 * XS;            // 4608
constexpr int WBUF = 8192;
constexpr int STAGEF = XBUF + WBUF;       // 12800 floats per stage
constexpr int NSTAGE = 4;                 // 51200 floats total
constexpr int OFF_H1 = 0;
constexpr int OFF_H2 = 256 * H1S;         // 34816
constexpr int OFF_W3 = OFF_H2 + 128 * H2S;// 52224 (> 4*12800 = 51200, no overlap)
constexpr int OFF_B1 = OFF_W3 + 2048;     // 54272
constexpr int OFF_B2 = OFF_B1 + 256;      // 54528
constexpr int OFF_B3 = OFF_B2 + 128;      // 54656
constexpr int SMEM_FLOATS = OFF_B3 + 16;  // 54672  (~214 KB)

__global__ __launch_bounds__(512, 1) void fused_kernel(
    const float* __restrict__ x, const float* __restrict__ b1,
    const float* __restrict__ b2, const float* __restrict__ b3,
    float* __restrict__ out) {
    extern __shared__ float smf[];
    const int tid = threadIdx.x, w = tid >> 5, lane = tid & 31;
    const int g = lane >> 2, q = lane & 3;
    const int m0 = blockIdx.x * 128;
    const uint32_t smb = (uint32_t)__cvta_generic_to_shared(smf);

    // phase 0: biases + w3 frags into smem (region above the stage ring)
    if (tid < 256) smf[OFF_B1 + tid] = b1[tid];
    if (tid < 128) smf[OFF_B2 + tid] = b2[tid];
    if (tid < 16)  smf[OFF_B3 + tid] = (tid < 10) ? b3[tid] : 0.f;
    ((float4*)(smf + OFF_W3))[tid] = g_w3p[tid];

    auto issue = [&](int t) {
        const int buf = t & 3;
        const char* wsrc = (const char*)g_w1p + (size_t)t * 32768;
        uint32_t wdst = smb + (uint32_t)(buf * STAGEF + XBUF) * 4u;
#pragma unroll
        for (int i = 0; i < 4; i++) {
            int idx = tid + i * 512;
            cpa16(wdst + idx * 16, wsrc + idx * 16);
        }
        uint32_t xdst = smb + (uint32_t)(buf * STAGEF) * 4u;
#pragma unroll
        for (int i = 0; i < 2; i++) {
            int idx = tid + i * 512;
            int row = idx >> 3, p = idx & 7, kk = t * 32 + p * 4;
            uint32_t dst = xdst + (uint32_t)(row * XS + p * 4) * 4u;
            const float* src = x + (size_t)(m0 + row) * 784 + kk;
            if (kk < 784) cpa16(dst, src);
            else          cpa16z(dst, x);
        }
        asm volatile("cp.async.commit_group;");
    };

    issue(0); issue(1); issue(2);

    const int wm = w >> 2, wn = w & 3;

    // ---------------- GEMM1: [256 n1] x [784 k] x [128 b] ----------------
    float acc[4][4][4];
#pragma unroll
    for (int a = 0; a < 4; a++)
#pragma unroll
        for (int b = 0; b < 4; b++)
#pragma unroll
            for (int c = 0; c < 4; c++) acc[a][b][c] = 0.f;

    for (int t = 0; t < 25; t++) {
        // tile t must be resident; allow the newest in-flight groups to float
        if (t <= 22)      asm volatile("cp.async.wait_group 2;");
        else if (t == 23) asm volatile("cp.async.wait_group 1;");
        else              asm volatile("cp.async.wait_group 0;");
        __syncthreads();
        // refill the buffer consumed in iteration t-1 (all warps passed it)
        if (t + 3 < 25) issue(t + 3);

        const int buf = t & 3;
        const float* Xb = smf + buf * STAGEF;
        const float4* Wb = (const float4*)(smf + buf * STAGEF + XBUF);
#pragma unroll
        for (int s = 0; s < 4; s++) {
            uint32_t a[4][4];
#pragma unroll
            for (int mf = 0; mf < 4; mf++) {
                float4 v = Wb[((s * 16 + wm * 4 + mf) * 8 + g) * 4 + q];
                a[mf][0] = __float_as_uint(v.x); a[mf][1] = __float_as_uint(v.y);
                a[mf][2] = __float_as_uint(v.z); a[mf][3] = __float_as_uint(v.w);
            }
            uint32_t bb[4][2];
#pragma unroll
            for (int nf = 0; nf < 4; nf++) {
                int bc = wn * 32 + nf * 8 + g;
                int k = s * 8 + q;
                bb[nf][0] = tf32u(Xb[bc * XS + k]);
                bb[nf][1] = tf32u(Xb[bc * XS + k + 4]);
            }
#pragma unroll
            for (int mf = 0; mf < 4; mf++)
#pragma unroll
                for (int nf = 0; nf < 4; nf++)
                    mma8(acc[mf][nf], a[mf][0], a[mf][1], a[mf][2], a[mf][3],
                         bb[nf][0], bb[nf][1]);
        }
    }
    __syncthreads();   // all warps done reading stage ring before h1T writes

    // epilogue 1: bias + relu + tf32-round -> h1T[n1][b]
#pragma unroll
    for (int mf = 0; mf < 4; mf++) {
        int n = wm * 64 + mf * 16 + g;
        float bi0 = smf[OFF_B1 + n], bi8 = smf[OFF_B1 + n + 8];
#pragma unroll
        for (int nf = 0; nf < 4; nf++) {
            int bc = wn * 32 + nf * 8 + 2 * q;
            smf[OFF_H1 + n * H1S + bc]           = tf32f(fmaxf(acc[mf][nf][0] + bi0, 0.f));
            smf[OFF_H1 + n * H1S + bc + 1]       = tf32f(fmaxf(acc[mf][nf][1] + bi0, 0.f));
            smf[OFF_H1 + (n + 8) * H1S + bc]     = tf32f(fmaxf(acc[mf][nf][2] + bi8, 0.f));
            smf[OFF_H1 + (n + 8) * H1S + bc + 1] = tf32f(fmaxf(acc[mf][nf][3] + bi8, 0.f));
        }
    }
    __syncthreads();

    // ---------------- GEMM2: [128 n2] x [256 k] x [128 b] ----------------
    float acc2[2][4][4];
#pragma unroll
    for (int a = 0; a < 2; a++)
#pragma unroll
        for (int b = 0; b < 4; b++)
#pragma unroll
            for (int c = 0; c < 4; c++) acc2[a][b][c] = 0.f;

#pragma unroll 4
    for (int s = 0; s < 32; s++) {
        uint32_t a[2][4];
#pragma unroll
        for (int mf = 0; mf < 2; mf++) {
            float4 v = g_w2p[((s * 8 + wm * 2 + mf) * 8 + g) * 4 + q];
            a[mf][0] = __float_as_uint(v.x); a[mf][1] = __float_as_uint(v.y);
            a[mf][2] = __float_as_uint(v.z); a[mf][3] = __float_as_uint(v.w);
        }
        uint32_t bb[4][2];
#pragma unroll
        for (int nf = 0; nf < 4; nf++) {
            int bc = wn * 32 + nf * 8 + g;
            int k = s * 8 + q;
            bb[nf][0] = __float_as_uint(smf[OFF_H1 + k * H1S + bc]);
            bb[nf][1] = __float_as_uint(smf[OFF_H1 + (k + 4) * H1S + bc]);
        }
#pragma unroll
        for (int mf = 0; mf < 2; mf++)
#pragma unroll
            for (int nf = 0; nf < 4; nf++)
                mma8(acc2[mf][nf], a[mf][0], a[mf][1], a[mf][2], a[mf][3],
                     bb[nf][0], bb[nf][1]);
    }

    // epilogue 2 -> h2T[n2][b]  (disjoint from h1T; no sync needed before writes)
#pragma unroll
    for (int mf = 0; mf < 2; mf++) {
        int n = wm * 32 + mf * 16 + g;
        float bi0 = smf[OFF_B2 + n], bi8 = smf[OFF_B2 + n + 8];
#pragma unroll
        for (int nf = 0; nf < 4; nf++) {
            int bc = wn * 32 + nf * 8 + 2 * q;
            smf[OFF_H2 + n * H2S + bc]           = tf32f(fmaxf(acc2[mf][nf][0] + bi0, 0.f));
            smf[OFF_H2 + n * H2S + bc + 1]       = tf32f(fmaxf(acc2[mf][nf][1] + bi0, 0.f));
            smf[OFF_H2 + (n + 8) * H2S + bc]     = tf32f(fmaxf(acc2[mf][nf][2] + bi8, 0.f));
            smf[OFF_H2 + (n + 8) * H2S + bc + 1] = tf32f(fmaxf(acc2[mf][nf][3] + bi8, 0.f));
        }
    }
    __syncthreads();

    // ---------------- GEMM3: [16 n3] x [128 k] x [128 b] ----------------
    float acc3[4] = {0.f, 0.f, 0.f, 0.f};
    const float4* W3s = (const float4*)(smf + OFF_W3);
#pragma unroll
    for (int s = 0; s < 16; s++) {
        float4 v = W3s[(s * 8 + g) * 4 + q];
        int k = s * 8 + q;
        int bc = w * 8 + g;
        uint32_t b0v = __float_as_uint(smf[OFF_H2 + k * H2S + bc]);
        uint32_t b1v = __float_as_uint(smf[OFF_H2 + (k + 4) * H2S + bc]);
        mma8(acc3, __float_as_uint(v.x), __float_as_uint(v.y),
                   __float_as_uint(v.z), __float_as_uint(v.w), b0v, b1v);
    }
    {
        int bc = w * 8 + 2 * q;
        float bi = smf[OFF_B3 + g];
        out[(size_t)(m0 + bc) * 10 + g]     = acc3[0] + bi;
        out[(size_t)(m0 + bc + 1) * 10 + g] = acc3[1] + bi;
        if (g + 8 < 10) {
            float bi8 = smf[OFF_B3 + g + 8];
            out[(size_t)(m0 + bc) * 10 + g + 8]     = acc3[2] + bi8;
            out[(size_t)(m0 + bc + 1) * 10 + g + 8] = acc3[3] + bi8;
        }
    }
}

// ---------------------------------------------------------------------------
extern "C" void kernel_launch(void* const* d_in, const int* in_sizes, int n_in,
                              void* d_out, int out_size) {
    const float* x    = (const float*)d_in[0];
    const float* conv = (const float*)d_in[1];
    const float* w1   = (const float*)d_in[2];
    const float* b1   = (const float*)d_in[3];
    const float* w2   = (const float*)d_in[4];
    const float* b2   = (const float*)d_in[5];
    const float* w3   = (const float*)d_in[6];
    const float* b3   = (const float*)d_in[7];
    float* out = (float*)d_out;

    prep_kernel<<<234, 256>>>(conv, w1, w2, w3);

    cudaFuncSetAttribute(fused_kernel, cudaFuncAttributeMaxDynamicSharedMemorySize,
                         SMEM_FLOATS * 4);
    fused_kernel<<<512, 512, SMEM_FLOATS * 4>>>(x, b1, b2, b3, out);
}

// round 5
// speedup vs baseline: 1.4337x; 1.4337x over previous
#include <cuda_runtime.h>
#include <cstdint>

#define DINL __device__ __forceinline__

// ---------------------------------------------------------------------------
// Precomputed weights in mma-fragment-friendly layouts (tf32-rounded fp32).
// g_w1p: GEMM1 A-operand = W_eff^T [256 x 800] as [kt(25)][ks(4)][grp(16)][r(8)][q(4)] float4
//        float4 = ( WT[n][k], WT[n+8][k], WT[n][k+4], WT[n+8][k+4] ),
//        n = grp*16+r, k = kt*32+ks*8+q.   (mma m16n8k8 A-frag ordering)
// g_w2p: GEMM2 A-operand = w2^T [128 x 256] as [ks(32)][grp(8)][r(8)][q(4)] float4
// g_w3p: GEMM3 A-operand = w3^T padded [16 x 128] as [ks(16)][r(8)][q(4)] float4
// ---------------------------------------------------------------------------
__device__ float4 g_w1p[25 * 4 * 16 * 8 * 4];   // 51200 float4
__device__ float4 g_w2p[32 * 8 * 8 * 4];        //  8192 float4
__device__ float4 g_w3p[16 * 8 * 4];            //   512 float4

DINL float tf32f(float f) { uint32_t u; asm("cvt.rna.tf32.f32 %0, %1;" : "=r"(u) : "f"(f)); return __uint_as_float(u); }
DINL uint32_t tf32u(float f) { uint32_t u; asm("cvt.rna.tf32.f32 %0, %1;" : "=r"(u) : "f"(f)); return u; }

DINL void mma8(float* c, uint32_t a0, uint32_t a1, uint32_t a2, uint32_t a3,
               uint32_t b0, uint32_t b1) {
    asm volatile(
        "mma.sync.aligned.m16n8k8.row.col.f32.tf32.tf32.f32 "
        "{%0,%1,%2,%3}, {%4,%5,%6,%7}, {%8,%9}, {%0,%1,%2,%3};"
        : "+f"(c[0]), "+f"(c[1]), "+f"(c[2]), "+f"(c[3])
        : "r"(a0), "r"(a1), "r"(a2), "r"(a3), "r"(b0), "r"(b1));
}

DINL void cpa16(uint32_t dst, const void* src) {
    asm volatile("cp.async.cg.shared.global [%0], [%1], 16;" :: "r"(dst), "l"(src));
}
DINL void cpa16z(uint32_t dst, const void* src) {
    asm volatile("cp.async.cg.shared.global [%0], [%1], 16, %2;" :: "r"(dst), "l"(src), "r"(0));
}

// ---------------------------------------------------------------------------
// Prep kernel: fold conv into fc1, transpose + tf32-round all weights.
// ---------------------------------------------------------------------------
DINL float weff(int k, int n, const float* cw, const float* w1) {
    if (k >= 784) return 0.f;
    int r = k / 28, c = k % 28;
    float acc = 0.f;
#pragma unroll
    for (int dr = 0; dr < 3; dr++)
#pragma unroll
        for (int dc = 0; dc < 3; dc++) {
            int rr = r - dr, cc = c - dc;
            if (rr >= 0 && rr < 26 && cc >= 0 && cc < 26)
                acc += cw[dr * 3 + dc] * w1[(rr * 26 + cc) * 256 + n];
        }
    return tf32f(acc);
}

__global__ __launch_bounds__(256) void prep_kernel(
    const float* __restrict__ cw, const float* __restrict__ w1,
    const float* __restrict__ w2, const float* __restrict__ w3) {
    int gid = blockIdx.x * 256 + threadIdx.x;
    if (blockIdx.x < 200) {
        int i = gid;                                    // 0..51199
        int q = i & 3, r = (i >> 2) & 7, mf = (i >> 5) & 15, ks = (i >> 9) & 3, kt = i >> 11;
        int k = kt * 32 + ks * 8 + q, n = mf * 16 + r;
        float4 v;
        v.x = weff(k, n, cw, w1);     v.y = weff(k, n + 8, cw, w1);
        v.z = weff(k + 4, n, cw, w1); v.w = weff(k + 4, n + 8, cw, w1);
        g_w1p[i] = v;
    } else if (blockIdx.x < 232) {
        int i = gid - 200 * 256;                        // 0..8191
        int q = i & 3, r = (i >> 2) & 7, mf = (i >> 5) & 7, ks = i >> 8;
        int k = ks * 8 + q, n = mf * 16 + r;
        float4 v;
        v.x = tf32f(w2[k * 128 + n]);       v.y = tf32f(w2[k * 128 + n + 8]);
        v.z = tf32f(w2[(k + 4) * 128 + n]); v.w = tf32f(w2[(k + 4) * 128 + n + 8]);
        g_w2p[i] = v;
    } else {
        int i = gid - 232 * 256;                        // 0..511
        if (i < 512) {
            int q = i & 3, r = (i >> 2) & 7, ks = i >> 5;
            int k = ks * 8 + q;
            float4 v;
            v.x = tf32f(w3[k * 10 + r]);
            v.y = (r + 8 < 10) ? tf32f(w3[k * 10 + r + 8]) : 0.f;
            v.z = tf32f(w3[(k + 4) * 10 + r]);
            v.w = (r + 8 < 10) ? tf32f(w3[(k + 4) * 10 + r + 8]) : 0.f;
            g_w3p[i] = v;
        }
    }
}

// ---------------------------------------------------------------------------
// Fused main kernel. 1024 threads (32 warps = 8 wm x 4 wn), 128 batch rows/CTA.
// Warp tile GEMM1: 32n x 32b.  Batch = N operand of mma.
// smem layout identical to before (stage ring aliased with h1T/h2T).
// ---------------------------------------------------------------------------
constexpr int XS = 36, H1S = 136, H2S = 136;
constexpr int XBUF = 128 * XS;            // 4608
constexpr int WBUF = 8192;
constexpr int STAGEF = XBUF + WBUF;       // 12800 floats per stage
constexpr int OFF_H1 = 0;
constexpr int OFF_H2 = 256 * H1S;         // 34816
constexpr int OFF_W3 = OFF_H2 + 128 * H2S;// 52224 (> 4*12800 = 51200, no overlap)
constexpr int OFF_B1 = OFF_W3 + 2048;     // 54272
constexpr int OFF_B2 = OFF_B1 + 256;      // 54528
constexpr int OFF_B3 = OFF_B2 + 128;      // 54656
constexpr int SMEM_FLOATS = OFF_B3 + 16;  // 54672  (~214 KB)

__global__ __launch_bounds__(1024, 1) void fused_kernel(
    const float* __restrict__ x, const float* __restrict__ b1,
    const float* __restrict__ b2, const float* __restrict__ b3,
    float* __restrict__ out) {
    extern __shared__ float smf[];
    const int tid = threadIdx.x, w = tid >> 5, lane = tid & 31;
    const int g = lane >> 2, q = lane & 3;
    const int m0 = blockIdx.x * 128;
    const uint32_t smb = (uint32_t)__cvta_generic_to_shared(smf);

    // phase 0: biases + w3 frags into smem (region above the stage ring)
    if (tid < 256) smf[OFF_B1 + tid] = b1[tid];
    if (tid < 128) smf[OFF_B2 + tid] = b2[tid];
    if (tid < 16)  smf[OFF_B3 + tid] = (tid < 10) ? b3[tid] : 0.f;
    if (tid < 512) ((float4*)(smf + OFF_W3))[tid] = g_w3p[tid];

    auto issue = [&](int t) {
        const int buf = t & 3;
        const char* wsrc = (const char*)g_w1p + (size_t)t * 32768;
        uint32_t wdst = smb + (uint32_t)(buf * STAGEF + XBUF) * 4u;
#pragma unroll
        for (int i = 0; i < 2; i++) {
            int idx = tid + i * 1024;
            cpa16(wdst + idx * 16, wsrc + idx * 16);
        }
        uint32_t xdst = smb + (uint32_t)(buf * STAGEF) * 4u;
        {
            int idx = tid;
            int row = idx >> 3, p = idx & 7, kk = t * 32 + p * 4;
            uint32_t dst = xdst + (uint32_t)(row * XS + p * 4) * 4u;
            const float* src = x + (size_t)(m0 + row) * 784 + kk;
            if (kk < 784) cpa16(dst, src);
            else          cpa16z(dst, x);
        }
        asm volatile("cp.async.commit_group;");
    };

    issue(0); issue(1); issue(2);

    const int wm = w >> 2, wn = w & 3;   // wm 0..7, wn 0..3

    // ---------------- GEMM1: [256 n1] x [784 k] x [128 b] ----------------
    // warp tile: n in [wm*32, wm*32+32), b in [wn*32, wn*32+32)
    float acc[2][4][4];
#pragma unroll
    for (int a = 0; a < 2; a++)
#pragma unroll
        for (int b = 0; b < 4; b++)
#pragma unroll
            for (int c = 0; c < 4; c++) acc[a][b][c] = 0.f;

    for (int t = 0; t < 25; t++) {
        if (t <= 22)      asm volatile("cp.async.wait_group 2;");
        else if (t == 23) asm volatile("cp.async.wait_group 1;");
        else              asm volatile("cp.async.wait_group 0;");
        __syncthreads();
        if (t + 3 < 25) issue(t + 3);

        const int buf = t & 3;
        const float* Xb = smf + buf * STAGEF;
        const float4* Wb = (const float4*)(smf + buf * STAGEF + XBUF);
#pragma unroll
        for (int s = 0; s < 4; s++) {
            uint32_t a[2][4];
#pragma unroll
            for (int mf = 0; mf < 2; mf++) {
                float4 v = Wb[((s * 16 + wm * 2 + mf) * 8 + g) * 4 + q];
                a[mf][0] = __float_as_uint(v.x); a[mf][1] = __float_as_uint(v.y);
                a[mf][2] = __float_as_uint(v.z); a[mf][3] = __float_as_uint(v.w);
            }
            uint32_t bb[4][2];
#pragma unroll
            for (int nf = 0; nf < 4; nf++) {
                int bc = wn * 32 + nf * 8 + g;
                int k = s * 8 + q;
                bb[nf][0] = tf32u(Xb[bc * XS + k]);
                bb[nf][1] = tf32u(Xb[bc * XS + k + 4]);
            }
#pragma unroll
            for (int mf = 0; mf < 2; mf++)
#pragma unroll
                for (int nf = 0; nf < 4; nf++)
                    mma8(acc[mf][nf], a[mf][0], a[mf][1], a[mf][2], a[mf][3],
                         bb[nf][0], bb[nf][1]);
        }
    }
    __syncthreads();   // all warps done reading stage ring before h1T writes

    // epilogue 1: bias + relu + tf32-round -> h1T[n1][b]
#pragma unroll
    for (int mf = 0; mf < 2; mf++) {
        int n = wm * 32 + mf * 16 + g;
        float bi0 = smf[OFF_B1 + n], bi8 = smf[OFF_B1 + n + 8];
#pragma unroll
        for (int nf = 0; nf < 4; nf++) {
            int bc = wn * 32 + nf * 8 + 2 * q;
            smf[OFF_H1 + n * H1S + bc]           = tf32f(fmaxf(acc[mf][nf][0] + bi0, 0.f));
            smf[OFF_H1 + n * H1S + bc + 1]       = tf32f(fmaxf(acc[mf][nf][1] + bi0, 0.f));
            smf[OFF_H1 + (n + 8) * H1S + bc]     = tf32f(fmaxf(acc[mf][nf][2] + bi8, 0.f));
            smf[OFF_H1 + (n + 8) * H1S + bc + 1] = tf32f(fmaxf(acc[mf][nf][3] + bi8, 0.f));
        }
    }
    __syncthreads();

    // ---------------- GEMM2: [128 n2] x [256 k] x [128 b] ----------------
    // warp tile: n2 in [wm*16, wm*16+16), b in [wn*32, wn*32+32)
    float acc2[4][4];
#pragma unroll
    for (int b = 0; b < 4; b++)
#pragma unroll
        for (int c = 0; c < 4; c++) acc2[b][c] = 0.f;

#pragma unroll 4
    for (int s = 0; s < 32; s++) {
        uint32_t a[4];
        {
            float4 v = g_w2p[((s * 8 + wm) * 8 + g) * 4 + q];
            a[0] = __float_as_uint(v.x); a[1] = __float_as_uint(v.y);
            a[2] = __float_as_uint(v.z); a[3] = __float_as_uint(v.w);
        }
        uint32_t bb[4][2];
#pragma unroll
        for (int nf = 0; nf < 4; nf++) {
            int bc = wn * 32 + nf * 8 + g;
            int k = s * 8 + q;
            bb[nf][0] = __float_as_uint(smf[OFF_H1 + k * H1S + bc]);
            bb[nf][1] = __float_as_uint(smf[OFF_H1 + (k + 4) * H1S + bc]);
        }
#pragma unroll
        for (int nf = 0; nf < 4; nf++)
            mma8(acc2[nf], a[0], a[1], a[2], a[3], bb[nf][0], bb[nf][1]);
    }

    // epilogue 2 -> h2T[n2][b]  (disjoint from h1T; no sync needed before writes)
    {
        int n = wm * 16 + g;
        float bi0 = smf[OFF_B2 + n], bi8 = smf[OFF_B2 + n + 8];
#pragma unroll
        for (int nf = 0; nf < 4; nf++) {
            int bc = wn * 32 + nf * 8 + 2 * q;
            smf[OFF_H2 + n * H2S + bc]           = tf32f(fmaxf(acc2[nf][0] + bi0, 0.f));
            smf[OFF_H2 + n * H2S + bc + 1]       = tf32f(fmaxf(acc2[nf][1] + bi0, 0.f));
            smf[OFF_H2 + (n + 8) * H2S + bc]     = tf32f(fmaxf(acc2[nf][2] + bi8, 0.f));
            smf[OFF_H2 + (n + 8) * H2S + bc + 1] = tf32f(fmaxf(acc2[nf][3] + bi8, 0.f));
        }
    }
    __syncthreads();

    // ---------------- GEMM3: [16 n3] x [128 k] x [128 b] ----------------
    // 16 active warps, 8 batch cols each
    if (w < 16) {
        float acc3[4] = {0.f, 0.f, 0.f, 0.f};
        const float4* W3s = (const float4*)(smf + OFF_W3);
#pragma unroll
        for (int s = 0; s < 16; s++) {
            float4 v = W3s[(s * 8 + g) * 4 + q];
            int k = s * 8 + q;
            int bc = w * 8 + g;
            uint32_t b0v = __float_as_uint(smf[OFF_H2 + k * H2S + bc]);
            uint32_t b1v = __float_as_uint(smf[OFF_H2 + (k + 4) * H2S + bc]);
            mma8(acc3, __float_as_uint(v.x), __float_as_uint(v.y),
                       __float_as_uint(v.z), __float_as_uint(v.w), b0v, b1v);
        }
        int bc = w * 8 + 2 * q;
        float bi = smf[OFF_B3 + g];
        out[(size_t)(m0 + bc) * 10 + g]     = acc3[0] + bi;
        out[(size_t)(m0 + bc + 1) * 10 + g] = acc3[1] + bi;
        if (g + 8 < 10) {
            float bi8 = smf[OFF_B3 + g + 8];
            out[(size_t)(m0 + bc) * 10 + g + 8]     = acc3[2] + bi8;
            out[(size_t)(m0 + bc + 1) * 10 + g + 8] = acc3[3] + bi8;
        }
    }
}

// ---------------------------------------------------------------------------
extern "C" void kernel_launch(void* const* d_in, const int* in_sizes, int n_in,
                              void* d_out, int out_size) {
    const float* x    = (const float*)d_in[0];
    const float* conv = (const float*)d_in[1];
    const float* w1   = (const float*)d_in[2];
    const float* b1   = (const float*)d_in[3];
    const float* w2   = (const float*)d_in[4];
    const float* b2   = (const float*)d_in[5];
    const float* w3   = (const float*)d_in[6];
    const float* b3   = (const float*)d_in[7];
    float* out = (float*)d_out;

    prep_kernel<<<234, 256>>>(conv, w1, w2, w3);

    cudaFuncSetAttribute(fused_kernel, cudaFuncAttributeMaxDynamicSharedMemorySize,
                         SMEM_FLOATS * 4);
    fused_kernel<<<512, 1024, SMEM_FLOATS * 4>>>(x, b1, b2, b3, out);
}

// round 6
// speedup vs baseline: 2.3396x; 1.6319x over previous
#include <cuda_runtime.h>
#include <cuda_fp16.h>
#include <cstdint>

#define DINL __device__ __forceinline__

// ---------------------------------------------------------------------------
// Prepacked fp16 A-operand fragment images (one uint4 = one lane's 16B of an
// m16n8k16 A-fragment: regs a0..a3 = {A[g][2t],A[g][2t+1]},{A[g+8][..]},
// {A[g][2t+8],..},{A[g+8][2t+8],..}).
// g_w1h: GEMM1 A = W_eff^T [256n x 800k]: [kt(25)][ks(2)][nb(16)][lane(32)]
// g_w2h: GEMM2 A = w2^T    [128n x 256k]: [ks(16)][nb(8)][lane]
// g_w3h: GEMM3 A = w3^T pad [16n x 128k]: [ks(8)][lane]
// ---------------------------------------------------------------------------
__device__ uint4 g_w1h[25 * 1024];
__device__ uint4 g_w2h[4096];
__device__ uint4 g_w3h[256];

DINL uint32_t h2pk(float lo, float hi) {
    uint32_t r;
    asm("cvt.rn.f16x2.f32 %0, %1, %2;" : "=r"(r) : "f"(hi), "f"(lo));
    return r;
}

DINL void mma16(float* c, const uint32_t* a, uint32_t b0, uint32_t b1) {
    asm volatile(
        "mma.sync.aligned.m16n8k16.row.col.f32.f16.f16.f32 "
        "{%0,%1,%2,%3}, {%4,%5,%6,%7}, {%8,%9}, {%0,%1,%2,%3};"
        : "+f"(c[0]), "+f"(c[1]), "+f"(c[2]), "+f"(c[3])
        : "r"(a[0]), "r"(a[1]), "r"(a[2]), "r"(a[3]), "r"(b0), "r"(b1));
}

DINL void ldm4(uint32_t* r, uint32_t addr) {
    asm volatile("ldmatrix.sync.aligned.m8n8.x4.shared.b16 {%0,%1,%2,%3}, [%4];"
                 : "=r"(r[0]), "=r"(r[1]), "=r"(r[2]), "=r"(r[3]) : "r"(addr));
}
DINL void ldm4t(uint32_t* r, uint32_t addr) {
    asm volatile("ldmatrix.sync.aligned.m8n8.x4.trans.shared.b16 {%0,%1,%2,%3}, [%4];"
                 : "=r"(r[0]), "=r"(r[1]), "=r"(r[2]), "=r"(r[3]) : "r"(addr));
}
DINL void ldm2t(uint32_t* r, uint32_t addr) {
    asm volatile("ldmatrix.sync.aligned.m8n8.x2.trans.shared.b16 {%0,%1}, [%2];"
                 : "=r"(r[0]), "=r"(r[1]) : "r"(addr));
}

DINL void lds128(uint32_t* r, uint32_t addr) {
    asm volatile("ld.shared.v4.b32 {%0,%1,%2,%3}, [%4];"
                 : "=r"(r[0]), "=r"(r[1]), "=r"(r[2]), "=r"(r[3]) : "r"(addr));
}
DINL void sts32(uint32_t addr, uint32_t v) {
    asm volatile("st.shared.b32 [%0], %1;" :: "r"(addr), "r"(v));
}
DINL void sts64(uint32_t addr, uint32_t v0, uint32_t v1) {
    asm volatile("st.shared.v2.b32 [%0], {%1,%2};" :: "r"(addr), "r"(v0), "r"(v1));
}
DINL void cpa16(uint32_t dst, const void* src) {
    asm volatile("cp.async.cg.shared.global [%0], [%1], 16;" :: "r"(dst), "l"(src));
}

// ---------------------------------------------------------------------------
// Prep: fold conv into fc1; pack all weights as fp16 fragment images.
// ---------------------------------------------------------------------------
DINL float weff(int k, int n, const float* cw, const float* w1) {
    if (k >= 784 || k < 0) return 0.f;
    int r = k / 28, c = k % 28;
    float acc = 0.f;
#pragma unroll
    for (int dr = 0; dr < 3; dr++)
#pragma unroll
        for (int dc = 0; dc < 3; dc++) {
            int rr = r - dr, cc = c - dc;
            if (rr >= 0 && rr < 26 && cc >= 0 && cc < 26)
                acc += cw[dr * 3 + dc] * w1[(rr * 26 + cc) * 256 + n];
        }
    return acc;
}

__global__ __launch_bounds__(256) void prep_kernel(
    const float* __restrict__ cw, const float* __restrict__ w1,
    const float* __restrict__ w2, const float* __restrict__ w3) {
    int gid = blockIdx.x * 256 + threadIdx.x;
    if (blockIdx.x < 100) {                       // 25600 units
        int u = gid;
        int t = u & 3, g = (u >> 2) & 7, nb = (u >> 5) & 15, ks = (u >> 9) & 1, kt = u >> 10;
        int n = nb * 16 + g, k = kt * 32 + ks * 16 + 2 * t;
        uint4 v;
        v.x = h2pk(weff(k, n, cw, w1),     weff(k + 1, n, cw, w1));
        v.y = h2pk(weff(k, n + 8, cw, w1), weff(k + 1, n + 8, cw, w1));
        v.z = h2pk(weff(k + 8, n, cw, w1), weff(k + 9, n, cw, w1));
        v.w = h2pk(weff(k + 8, n + 8, cw, w1), weff(k + 9, n + 8, cw, w1));
        g_w1h[u] = v;
    } else if (blockIdx.x < 116) {                // 4096 units
        int u = gid - 100 * 256;
        int t = u & 3, g = (u >> 2) & 7, nb = (u >> 5) & 7, ks = u >> 8;
        int n = nb * 16 + g, k = ks * 16 + 2 * t;
        uint4 v;
        v.x = h2pk(w2[k * 128 + n],           w2[(k + 1) * 128 + n]);
        v.y = h2pk(w2[k * 128 + n + 8],       w2[(k + 1) * 128 + n + 8]);
        v.z = h2pk(w2[(k + 8) * 128 + n],     w2[(k + 9) * 128 + n]);
        v.w = h2pk(w2[(k + 8) * 128 + n + 8], w2[(k + 9) * 128 + n + 8]);
        g_w2h[u] = v;
    } else {                                      // 256 units
        int u = gid - 116 * 256;
        if (u < 256) {
            int t = u & 3, g = (u >> 2) & 7, ks = u >> 5;
            int k = ks * 16 + 2 * t;
            bool hi = (g + 8) < 10;
            uint4 v;
            v.x = h2pk(w3[k * 10 + g], w3[(k + 1) * 10 + g]);
            v.y = hi ? h2pk(w3[k * 10 + g + 8], w3[(k + 1) * 10 + g + 8]) : 0u;
            v.z = h2pk(w3[(k + 8) * 10 + g], w3[(k + 9) * 10 + g]);
            v.w = hi ? h2pk(w3[(k + 8) * 10 + g + 8], w3[(k + 9) * 10 + g + 8]) : 0u;
            g_w3h[u] = v;
        }
    }
}

// ---------------------------------------------------------------------------
// Fused main kernel. 1024 threads = 32 warps (8 wm x 4 wn). 128 batch rows/CTA.
// GEMM1 warp tile 32n x 32b, fp16 m16n8k16, batch = mma N operand.
// ---------------------------------------------------------------------------
constexpr int XPITCH = 40;                         // halves (80B rows, conflict-free ldmatrix)
constexpr int XSTG = 128 * XPITCH * 2;             // 10240 B
constexpr int WSTG = 16384;
constexpr int STG = XSTG + WSTG;                   // 26624 B
constexpr int OFF_Wt = XSTG;
// post-GEMM1 regions (ring [0, 4*STG)=106496 is dead before these are written)
constexpr int OFF_H1 = 0;                          // [256k][136h] = 69632 B
constexpr int OFF_W2 = 69632;                      // 65536 B
constexpr int OFF_W3 = 135168;                     // 4096 B
constexpr int OFF_H2 = 139264;                     // [128k][136h] = 34816 B -> 174080
constexpr int OFF_B1 = 174080;                     // 256 f32
constexpr int OFF_B2 = 175104;                     // 128 f32
constexpr int OFF_B3 = 175616;                     // 16 f32
constexpr int SMEMB = 175744;

__global__ __launch_bounds__(1024, 1) void fused_kernel(
    const float* __restrict__ x, const float* __restrict__ b1,
    const float* __restrict__ b2, const float* __restrict__ b3,
    float* __restrict__ out) {
    extern __shared__ char sm[];
    const uint32_t smb = (uint32_t)__cvta_generic_to_shared(sm);
    const int tid = threadIdx.x, w = tid >> 5, lane = tid & 31;
    const int g = lane >> 2, q = lane & 3;
    const int wm = w >> 2, wn = w & 3;
    const int m0 = blockIdx.x * 128;
    float* B1f = (float*)(sm + OFF_B1);
    float* B2f = (float*)(sm + OFF_B2);
    float* B3f = (float*)(sm + OFF_B3);

    if (tid < 256) B1f[tid] = b1[tid];
    if (tid < 128) B2f[tid] = b2[tid];
    if (tid < 16)  B3f[tid] = (tid < 10) ? b3[tid] : 0.f;

    // x load/convert path: thread owns (row = tid>>3, 4 halves at col (tid&7)*4)
    const int xr = tid >> 3, xc = (tid & 7) * 4;
    const float* xrow = x + (size_t)(m0 + xr) * 784;

    float4 fb;
    auto ldgx = [&](int t) {
        int col = t * 32 + xc;
        if (col < 784) fb = *(const float4*)(xrow + col);
        else           fb = make_float4(0.f, 0.f, 0.f, 0.f);
    };
    auto stsx = [&](int t) {
        uint32_t d = smb + (uint32_t)((t & 3) * STG + xr * (XPITCH * 2) + xc * 2);
        sts64(d, h2pk(fb.x, fb.y), h2pk(fb.z, fb.w));
    };
    auto issueW = [&](int t) {
        uint32_t d = smb + (uint32_t)((t & 3) * STG + OFF_Wt + tid * 16);
        cpa16(d, (const char*)g_w1h + (size_t)t * 16384 + tid * 16);
        asm volatile("cp.async.commit_group;");
    };

    // prologue: stages 0..2 direct, prefetch regs for 3
    for (int t = 0; t < 3; t++) { ldgx(t); stsx(t); issueW(t); }
    ldgx(3);

    // ---------------- GEMM1: [256n] x [800k] x [128b] ----------------
    float acc[2][4][4];
#pragma unroll
    for (int a = 0; a < 2; a++)
#pragma unroll
        for (int b = 0; b < 4; b++)
#pragma unroll
            for (int c = 0; c < 4; c++) acc[a][b][c] = 0.f;

    for (int t = 0; t < 25; t++) {
        if (t <= 22)      asm volatile("cp.async.wait_group 2;");
        else if (t == 23) asm volatile("cp.async.wait_group 1;");
        else              asm volatile("cp.async.wait_group 0;");
        __syncthreads();
        if (t + 3 < 25) { stsx(t + 3); issueW(t + 3); }
        if (t + 4 < 25) ldgx(t + 4);

        const uint32_t xs = smb + (uint32_t)((t & 3) * STG);
        const uint32_t ws = xs + OFF_Wt;
#pragma unroll
        for (int ks = 0; ks < 2; ks++) {
            uint32_t A[2][4];
#pragma unroll
            for (int mf = 0; mf < 2; mf++)
                lds128(A[mf], ws + (uint32_t)(((ks * 16 + wm * 2 + mf) * 32 + lane) * 16));
#pragma unroll
            for (int nfp = 0; nfp < 2; nfp++) {
                uint32_t B[4];
                uint32_t badr = xs
                    + (uint32_t)((wn * 32 + nfp * 16 + (lane & 7) + ((lane >> 4) & 1) * 8) * (XPITCH * 2)
                                 + ks * 32 + ((lane >> 3) & 1) * 16);
                ldm4(B, badr);
                mma16(acc[0][nfp * 2],     A[0], B[0], B[1]);
                mma16(acc[0][nfp * 2 + 1], A[0], B[2], B[3]);
                mma16(acc[1][nfp * 2],     A[1], B[0], B[1]);
                mma16(acc[1][nfp * 2 + 1], A[1], B[2], B[3]);
            }
        }
    }
    __syncthreads();   // ring fully consumed; safe to overwrite with h1/w2

    // prefetch w2/w3 fragment images (overlaps epilogue 1)
#pragma unroll
    for (int i = 0; i < 4; i++) {
        int idx = tid + i * 1024;
        cpa16(smb + OFF_W2 + idx * 16, g_w2h + idx);
    }
    if (tid < 256) cpa16(smb + OFF_W3 + tid * 16, g_w3h + tid);
    asm volatile("cp.async.commit_group;");

    // epilogue 1: relu(acc+b1) -> h1 fp16 [k=n1 rows, pitch 136h][b]
#pragma unroll
    for (int mf = 0; mf < 2; mf++) {
        int n = wm * 32 + mf * 16 + g;
        float bi0 = B1f[n], bi8 = B1f[n + 8];
#pragma unroll
        for (int nf = 0; nf < 4; nf++) {
            int bc = wn * 32 + nf * 8 + 2 * q;
            float* a = acc[mf][nf];
            sts32(smb + (uint32_t)(OFF_H1 + n * 272 + bc * 2),
                  h2pk(fmaxf(a[0] + bi0, 0.f), fmaxf(a[1] + bi0, 0.f)));
            sts32(smb + (uint32_t)(OFF_H1 + (n + 8) * 272 + bc * 2),
                  h2pk(fmaxf(a[2] + bi8, 0.f), fmaxf(a[3] + bi8, 0.f)));
        }
    }
    asm volatile("cp.async.wait_group 0;");
    __syncthreads();

    // ---------------- GEMM2: [128n2] x [256k] x [128b] ----------------
    float a2[4][4];
#pragma unroll
    for (int b = 0; b < 4; b++)
#pragma unroll
        for (int c = 0; c < 4; c++) a2[b][c] = 0.f;

#pragma unroll 4
    for (int ks = 0; ks < 16; ks++) {
        uint32_t A[4];
        lds128(A, smb + (uint32_t)(OFF_W2 + ((ks * 8 + wm) * 32 + lane) * 16));
#pragma unroll
        for (int nfp = 0; nfp < 2; nfp++) {
            uint32_t B[4];
            uint32_t badr = smb
                + (uint32_t)(OFF_H1 + (ks * 16 + (lane & 7) + ((lane >> 3) & 1) * 8) * 272
                             + (wn * 32 + nfp * 16 + ((lane >> 4) & 1) * 8) * 2);
            ldm4t(B, badr);
            mma16(a2[nfp * 2],     A, B[0], B[1]);
            mma16(a2[nfp * 2 + 1], A, B[2], B[3]);
        }
    }

    // epilogue 2: relu(a2+b2) -> h2 fp16 [k=n2 rows][b]   (disjoint from h1)
    {
        int n = wm * 16 + g;
        float bi0 = B2f[n], bi8 = B2f[n + 8];
#pragma unroll
        for (int nf = 0; nf < 4; nf++) {
            int bc = wn * 32 + nf * 8 + 2 * q;
            float* a = a2[nf];
            sts32(smb + (uint32_t)(OFF_H2 + n * 272 + bc * 2),
                  h2pk(fmaxf(a[0] + bi0, 0.f), fmaxf(a[1] + bi0, 0.f)));
            sts32(smb + (uint32_t)(OFF_H2 + (n + 8) * 272 + bc * 2),
                  h2pk(fmaxf(a[2] + bi8, 0.f), fmaxf(a[3] + bi8, 0.f)));
        }
    }
    __syncthreads();

    // ---------------- GEMM3: [16n3] x [128k] x [128b], 16 warps x 8b ----------
    if (w < 16) {
        float a3[4] = {0.f, 0.f, 0.f, 0.f};
#pragma unroll
        for (int ks = 0; ks < 8; ks++) {
            uint32_t A[4];
            lds128(A, smb + (uint32_t)(OFF_W3 + (ks * 32 + lane) * 16));
            uint32_t B[2];
            int l = lane & 15;
            uint32_t badr = smb
                + (uint32_t)(OFF_H2 + (ks * 16 + (l & 7) + ((l >> 3) & 1) * 8) * 272 + w * 16);
            ldm2t(B, badr);
            mma16(a3, A, B[0], B[1]);
        }
        int b = m0 + w * 8 + 2 * q;
        out[(size_t)b * 10 + g]       = a3[0] + B3f[g];
        out[(size_t)(b + 1) * 10 + g] = a3[1] + B3f[g];
        if (g < 2) {
            out[(size_t)b * 10 + g + 8]       = a3[2] + B3f[g + 8];
            out[(size_t)(b + 1) * 10 + g + 8] = a3[3] + B3f[g + 8];
        }
    }
}

// ---------------------------------------------------------------------------
extern "C" void kernel_launch(void* const* d_in, const int* in_sizes, int n_in,
                              void* d_out, int out_size) {
    const float* x    = (const float*)d_in[0];
    const float* conv = (const float*)d_in[1];
    const float* w1   = (const float*)d_in[2];
    const float* b1   = (const float*)d_in[3];
    const float* w2   = (const float*)d_in[4];
    const float* b2   = (const float*)d_in[5];
    const float* w3   = (const float*)d_in[6];
    const float* b3   = (const float*)d_in[7];
    float* out = (float*)d_out;

    prep_kernel<<<117, 256>>>(conv, w1, w2, w3);

    cudaFuncSetAttribute(fused_kernel, cudaFuncAttributeMaxDynamicSharedMemorySize, SMEMB);
    fused_kernel<<<512, 1024, SMEMB>>>(x, b1, b2, b3, out);
}